// round 2
// baseline (speedup 1.0000x reference)
#include <cuda_runtime.h>
#include <math.h>

// ---------------- problem constants ----------------
#define HIDDEN    2048
#define KVDIM     512
#define HEAD_DIM  128
#define NUM_HEADS 16
#define NUM_KV    4
#define GROUP     4
#define SEQ       2048
#define BATCH     2
#define MTOT      (BATCH * SEQ)          // 4096
#define ATT_SCALE 0.08838834764831845f   // 128^-0.5

// ---------------- scratch (no allocations allowed) ----------------
__device__ float g_Q [MTOT * HIDDEN];    // 32 MB
__device__ float g_K [MTOT * KVDIM];     // 8 MB
__device__ float g_V [MTOT * KVDIM];     // 8 MB
__device__ float g_AO[MTOT * HIDDEN];    // 32 MB

// ============================================================
// Tiled SGEMM with bias: C[M,N] = A[M,K] @ W[K,N] + bias[N]
// BM=128, BN=128, BK=8, 256 threads, 8x8 per-thread tile.
// ============================================================
#define BM 128
#define BN 128
#define BKQ 8

__global__ __launch_bounds__(256)
void gemm_bias_kernel(const float* __restrict__ A,
                      const float* __restrict__ W,
                      const float* __restrict__ bias,
                      float* __restrict__ C,
                      int M, int N, int K)
{
    __shared__ float As[BKQ][BM];   // [k][m]
    __shared__ float Bs[BKQ][BN];   // [k][n]

    const int tid = threadIdx.x;
    const int tx  = tid & 15;       // 0..15 -> n
    const int ty  = tid >> 4;       // 0..15 -> m
    const int bm  = blockIdx.y * BM;
    const int bn  = blockIdx.x * BN;

    float acc[8][8];
    #pragma unroll
    for (int i = 0; i < 8; i++)
        #pragma unroll
        for (int j = 0; j < 8; j++) acc[i][j] = 0.0f;

    // A tile load mapping: 128 rows x 8 cols -> one float4 per thread
    const int a_row = tid >> 1;            // 0..127
    const int a_col = (tid & 1) * 4;       // 0 or 4
    // B tile load mapping: 8 rows x 128 cols -> one float4 per thread
    const int b_row = tid >> 5;            // 0..7
    const int b_col = (tid & 31) * 4;      // 0..124

    const float* Aptr = A + (size_t)(bm + a_row) * K + a_col;

    for (int k0 = 0; k0 < K; k0 += BKQ) {
        float4 av = *(const float4*)(Aptr + k0);
        float4 bv = *(const float4*)(W + (size_t)(k0 + b_row) * N + bn + b_col);

        As[a_col + 0][a_row] = av.x;
        As[a_col + 1][a_row] = av.y;
        As[a_col + 2][a_row] = av.z;
        As[a_col + 3][a_row] = av.w;
        *(float4*)&Bs[b_row][b_col] = bv;
        __syncthreads();

        #pragma unroll
        for (int kk = 0; kk < BKQ; kk++) {
            float ar[8], br[8];
            *(float4*)(ar    ) = *(const float4*)&As[kk][ty * 8    ];
            *(float4*)(ar + 4) = *(const float4*)&As[kk][ty * 8 + 4];
            *(float4*)(br    ) = *(const float4*)&Bs[kk][tx * 8    ];
            *(float4*)(br + 4) = *(const float4*)&Bs[kk][tx * 8 + 4];
            #pragma unroll
            for (int i = 0; i < 8; i++)
                #pragma unroll
                for (int j = 0; j < 8; j++)
                    acc[i][j] = fmaf(ar[i], br[j], acc[i][j]);
        }
        __syncthreads();
    }

    // epilogue: bias + store
    #pragma unroll
    for (int i = 0; i < 8; i++) {
        const int row = bm + ty * 8 + i;
        float* crow = C + (size_t)row * N + bn + tx * 8;
        #pragma unroll
        for (int j = 0; j < 8; j += 4) {
            float4 v;
            v.x = acc[i][j + 0] + bias[bn + tx * 8 + j + 0];
            v.y = acc[i][j + 1] + bias[bn + tx * 8 + j + 1];
            v.z = acc[i][j + 2] + bias[bn + tx * 8 + j + 2];
            v.w = acc[i][j + 3] + bias[bn + tx * 8 + j + 3];
            *(float4*)(crow + j) = v;
        }
    }
}

// ============================================================
// Flash attention (fp32, non-causal), 1 CTA per (b, head, 64-q block)
// BQ=64, BK=64, 256 threads.
// ============================================================
#define BQ 64
#define BK 64
#define QPAD 4   // keep 16B alignment for float4 row reads

struct FlashSmem {
    float Qs[HEAD_DIM][BQ + QPAD];   // [d][r], pre-scaled by ATT_SCALE
    float Ks[HEAD_DIM][BK + QPAD];   // [d][j]
    float Vs[BK][HEAD_DIM];          // [j][d]
    float Ss[BQ][BK + 1];            // scores / probabilities (scalar access only)
    float mrow[BQ];
    float lrow[BQ];
    float frow[BQ];
};

__global__ __launch_bounds__(256)
void flash_attn_kernel(const float* __restrict__ Q,
                       const float* __restrict__ K,
                       const float* __restrict__ V,
                       float* __restrict__ O)
{
    extern __shared__ char smem_raw[];
    FlashSmem& sm = *reinterpret_cast<FlashSmem*>(smem_raw);

    const int tid = threadIdx.x;
    const int tx  = tid & 15;     // 0..15
    const int ty  = tid >> 4;     // 0..15
    const int qb  = blockIdx.x;   // 0..31
    const int h   = blockIdx.y;   // 0..15
    const int b   = blockIdx.z;   // 0..1
    const int kvh = h >> 2;       // GROUP = 4

    const size_t q_base = ((size_t)(b * SEQ + qb * BQ)) * HIDDEN + h * HEAD_DIM;
    const size_t k_base = ((size_t)(b * SEQ)) * KVDIM + kvh * HEAD_DIM;

    // load Q block (pre-scaled)
    for (int idx = tid; idx < BQ * HEAD_DIM; idx += 256) {
        int r = idx >> 7;          // /128
        int d = idx & 127;
        sm.Qs[d][r] = Q[q_base + (size_t)r * HIDDEN + d] * ATT_SCALE;
    }
    if (tid < BQ) {
        sm.mrow[tid] = -INFINITY;
        sm.lrow[tid] = 0.0f;
    }

    float acc[4][8];               // rows ty*4+i, dims tx*8+jj
    #pragma unroll
    for (int i = 0; i < 4; i++)
        #pragma unroll
        for (int j = 0; j < 8; j++) acc[i][j] = 0.0f;

    for (int kb = 0; kb < SEQ / BK; kb++) {
        __syncthreads();   // previous iteration done with Ks/Vs/Ss
        // load K/V block
        const size_t kv_off = k_base + (size_t)kb * BK * KVDIM;
        for (int idx = tid; idx < BK * HEAD_DIM; idx += 256) {
            int j = idx >> 7;
            int d = idx & 127;
            float kv = K[kv_off + (size_t)j * KVDIM + d];
            float vv = V[kv_off + (size_t)j * KVDIM + d];
            sm.Ks[d][j] = kv;
            sm.Vs[j][d] = vv;
        }
        __syncthreads();

        // scores: S = Qs^T @ Ks  (4x4 per thread)
        {
            float s[4][4];
            #pragma unroll
            for (int i = 0; i < 4; i++)
                #pragma unroll
                for (int j = 0; j < 4; j++) s[i][j] = 0.0f;

            #pragma unroll 4
            for (int d = 0; d < HEAD_DIM; d++) {
                float q4[4], k4[4];
                *(float4*)q4 = *(const float4*)&sm.Qs[d][ty * 4];
                *(float4*)k4 = *(const float4*)&sm.Ks[d][tx * 4];
                #pragma unroll
                for (int i = 0; i < 4; i++)
                    #pragma unroll
                    for (int j = 0; j < 4; j++)
                        s[i][j] = fmaf(q4[i], k4[j], s[i][j]);
            }
            #pragma unroll
            for (int i = 0; i < 4; i++)
                #pragma unroll
                for (int j = 0; j < 4; j++)
                    sm.Ss[ty * 4 + i][tx * 4 + j] = s[i][j];
        }
        __syncthreads();

        // online softmax, one thread per row (threads 0..63)
        if (tid < BQ) {
            const int r = tid;
            float rowmax = -INFINITY;
            #pragma unroll 8
            for (int j = 0; j < BK; j++)
                rowmax = fmaxf(rowmax, sm.Ss[r][j]);
            float m_old = sm.mrow[r];
            float m_new = fmaxf(m_old, rowmax);
            float f     = __expf(m_old - m_new);   // 0 when m_old = -inf
            float sum   = 0.0f;
            #pragma unroll 8
            for (int j = 0; j < BK; j++) {
                float p = __expf(sm.Ss[r][j] - m_new);
                sm.Ss[r][j] = p;
                sum += p;
            }
            sm.mrow[r] = m_new;
            sm.lrow[r] = sm.lrow[r] * f + sum;
            sm.frow[r] = f;
        }
        __syncthreads();

        // rescale accumulators, then acc += P @ V
        float fr[4];
        #pragma unroll
        for (int i = 0; i < 4; i++) fr[i] = sm.frow[ty * 4 + i];
        #pragma unroll
        for (int i = 0; i < 4; i++)
            #pragma unroll
            for (int jj = 0; jj < 8; jj++) acc[i][jj] *= fr[i];

        #pragma unroll 4
        for (int j = 0; j < BK; j++) {
            float p[4];
            #pragma unroll
            for (int i = 0; i < 4; i++) p[i] = sm.Ss[ty * 4 + i][j];
            float v[8];
            *(float4*)(v    ) = *(const float4*)&sm.Vs[j][tx * 8    ];
            *(float4*)(v + 4) = *(const float4*)&sm.Vs[j][tx * 8 + 4];
            #pragma unroll
            for (int i = 0; i < 4; i++)
                #pragma unroll
                for (int jj = 0; jj < 8; jj++)
                    acc[i][jj] = fmaf(p[i], v[jj], acc[i][jj]);
        }
    }

    __syncthreads();
    // final normalization + store
    #pragma unroll
    for (int i = 0; i < 4; i++) {
        const int r = ty * 4 + i;
        const float inv_l = 1.0f / sm.lrow[r];
        float* orow = O + q_base + (size_t)r * HIDDEN + tx * 8;
        #pragma unroll
        for (int jj = 0; jj < 8; jj += 4) {
            float4 v;
            v.x = acc[i][jj + 0] * inv_l;
            v.y = acc[i][jj + 1] * inv_l;
            v.z = acc[i][jj + 2] * inv_l;
            v.w = acc[i][jj + 3] * inv_l;
            *(float4*)(orow + jj) = v;
        }
    }
}

// ============================================================
// launcher
// ============================================================
extern "C" void kernel_launch(void* const* d_in, const int* in_sizes, int n_in,
                              void* d_out, int out_size)
{
    const float* x  = (const float*)d_in[0];
    const float* Wq = (const float*)d_in[1];
    const float* bq = (const float*)d_in[2];
    const float* Wk = (const float*)d_in[3];
    const float* bk = (const float*)d_in[4];
    const float* Wv = (const float*)d_in[5];
    const float* bv = (const float*)d_in[6];
    const float* Wo = (const float*)d_in[7];
    const float* bo = (const float*)d_in[8];
    float* out = (float*)d_out;

    float *dQ, *dK, *dV, *dAO;
    cudaGetSymbolAddress((void**)&dQ,  g_Q);
    cudaGetSymbolAddress((void**)&dK,  g_K);
    cudaGetSymbolAddress((void**)&dV,  g_V);
    cudaGetSymbolAddress((void**)&dAO, g_AO);

    const int M = MTOT, Kdim = HIDDEN;

    dim3 gq(HIDDEN / BN, M / BM);   // 16 x 32
    dim3 gkv(KVDIM / BN, M / BM);   //  4 x 32
    gemm_bias_kernel<<<gq,  256>>>(x, Wq, bq, dQ, M, HIDDEN, Kdim);
    gemm_bias_kernel<<<gkv, 256>>>(x, Wk, bk, dK, M, KVDIM,  Kdim);
    gemm_bias_kernel<<<gkv, 256>>>(x, Wv, bv, dV, M, KVDIM,  Kdim);

    static_assert(sizeof(FlashSmem) < 227 * 1024, "smem too big");
    cudaFuncSetAttribute(flash_attn_kernel,
                         cudaFuncAttributeMaxDynamicSharedMemorySize,
                         (int)sizeof(FlashSmem));
    dim3 ga(SEQ / BQ, NUM_HEADS, BATCH);   // 32 x 16 x 2
    flash_attn_kernel<<<ga, 256, sizeof(FlashSmem)>>>(dQ, dK, dV, dAO);

    gemm_bias_kernel<<<gq, 256>>>(dAO, Wo, bo, out, M, HIDDEN, Kdim);
}

// round 4
// speedup vs baseline: 1.4171x; 1.4171x over previous
#include <cuda_runtime.h>
#include <cuda_bf16.h>
#include <math.h>
#include <stdint.h>

// ---------------- problem constants ----------------
#define HIDDEN    2048
#define KVDIM     512
#define HEAD_DIM  128
#define NUM_HEADS 16
#define SEQ       2048
#define BATCH     2
#define MTOT      (BATCH * SEQ)          // 4096
#define ATT_SCALE 0.08838834764831845f   // 128^-0.5
#define KDIM      2048                   // K of every GEMM

// ---------------- scratch (no allocations allowed) ----------------
__device__ float g_Q [MTOT * HIDDEN];
__device__ float g_K [MTOT * KVDIM];
__device__ float g_V [MTOT * KVDIM];
__device__ float g_AO[MTOT * HIDDEN];

__device__ __nv_bfloat16 g_xh [MTOT * HIDDEN];   // split x / AO (reused)
__device__ __nv_bfloat16 g_xl [MTOT * HIDDEN];
__device__ __nv_bfloat16 g_wqt_h[HIDDEN * HIDDEN];  // W^T [N,K] splits
__device__ __nv_bfloat16 g_wqt_l[HIDDEN * HIDDEN];
__device__ __nv_bfloat16 g_wkt_h[KVDIM  * HIDDEN];
__device__ __nv_bfloat16 g_wkt_l[KVDIM  * HIDDEN];
__device__ __nv_bfloat16 g_wvt_h[KVDIM  * HIDDEN];
__device__ __nv_bfloat16 g_wvt_l[KVDIM  * HIDDEN];
__device__ __nv_bfloat16 g_wot_h[HIDDEN * HIDDEN];
__device__ __nv_bfloat16 g_wot_l[HIDDEN * HIDDEN];

// ============================================================
// PTX helpers (compute_103-safe: cp.async + ldmatrix + mma.sync only)
// ============================================================
__device__ __forceinline__ uint32_t smem_u32(const void* p) {
    return (uint32_t)__cvta_generic_to_shared(p);
}
__device__ __forceinline__ void cp_async16(uint32_t dst, const void* src) {
    asm volatile("cp.async.cg.shared.global [%0], [%1], 16;"
                 :: "r"(dst), "l"(src) : "memory");
}
__device__ __forceinline__ void cp_commit() {
    asm volatile("cp.async.commit_group;" ::: "memory");
}
__device__ __forceinline__ void cp_wait1() {
    asm volatile("cp.async.wait_group 1;" ::: "memory");
}
__device__ __forceinline__ void cp_wait0() {
    asm volatile("cp.async.wait_group 0;" ::: "memory");
}
__device__ __forceinline__ void ldm_x4(uint32_t* r, uint32_t addr) {
    asm volatile("ldmatrix.sync.aligned.m8n8.x4.shared.b16 {%0,%1,%2,%3}, [%4];"
                 : "=r"(r[0]), "=r"(r[1]), "=r"(r[2]), "=r"(r[3]) : "r"(addr));
}
__device__ __forceinline__ void mma_bf16(float* c, const uint32_t* a, const uint32_t* b) {
    asm volatile(
        "mma.sync.aligned.m16n8k16.row.col.f32.bf16.bf16.f32 "
        "{%0,%1,%2,%3}, {%4,%5,%6,%7}, {%8,%9}, {%0,%1,%2,%3};"
        : "+f"(c[0]), "+f"(c[1]), "+f"(c[2]), "+f"(c[3])
        : "r"(a[0]), "r"(a[1]), "r"(a[2]), "r"(a[3]), "r"(b[0]), "r"(b[1]));
}

// ============================================================
// split / transpose kernels
// ============================================================
__global__ void split_kernel(const float* __restrict__ src,
                             __nv_bfloat16* __restrict__ hi,
                             __nv_bfloat16* __restrict__ lo, int n4)
{
    int i = blockIdx.x * 256 + threadIdx.x;
    if (i >= n4) return;
    float4 v = *(const float4*)(src + (size_t)i * 4);
    __nv_bfloat16 h0 = __float2bfloat16(v.x);
    __nv_bfloat16 h1 = __float2bfloat16(v.y);
    __nv_bfloat16 h2 = __float2bfloat16(v.z);
    __nv_bfloat16 h3 = __float2bfloat16(v.w);
    __nv_bfloat16 l0 = __float2bfloat16(v.x - __bfloat162float(h0));
    __nv_bfloat16 l1 = __float2bfloat16(v.y - __bfloat162float(h1));
    __nv_bfloat16 l2 = __float2bfloat16(v.z - __bfloat162float(h2));
    __nv_bfloat16 l3 = __float2bfloat16(v.w - __bfloat162float(h3));
    ushort4 hv = make_ushort4(__bfloat16_as_ushort(h0), __bfloat16_as_ushort(h1),
                              __bfloat16_as_ushort(h2), __bfloat16_as_ushort(h3));
    ushort4 lv = make_ushort4(__bfloat16_as_ushort(l0), __bfloat16_as_ushort(l1),
                              __bfloat16_as_ushort(l2), __bfloat16_as_ushort(l3));
    *(ushort4*)(hi + (size_t)i * 4) = hv;
    *(ushort4*)(lo + (size_t)i * 4) = lv;
}

// W [K, N] (row-major) -> T [N, K] split into hi/lo bf16
__global__ void transpose_split_kernel(const float* __restrict__ W,
                                       __nv_bfloat16* __restrict__ Th,
                                       __nv_bfloat16* __restrict__ Tl,
                                       int Kr, int Nc)
{
    __shared__ float t[32][33];
    const int tx = threadIdx.x;
    const int ty = threadIdx.y;
    const int n0 = blockIdx.x * 32;
    const int k0 = blockIdx.y * 32;

    #pragma unroll
    for (int i = 0; i < 4; i++) {
        int kk = ty + i * 8;
        t[kk][tx] = W[(size_t)(k0 + kk) * Nc + n0 + tx];
    }
    __syncthreads();
    #pragma unroll
    for (int i = 0; i < 4; i++) {
        int rr = ty + i * 8;
        float v = t[tx][rr];
        __nv_bfloat16 h = __float2bfloat16(v);
        __nv_bfloat16 l = __float2bfloat16(v - __bfloat162float(h));
        size_t o = (size_t)(n0 + rr) * Kr + k0 + tx;
        Th[o] = h;
        Tl[o] = l;
    }
}

// ============================================================
// HMMA bf16x2 GEMM: C[M,N] = (Ah+Al)[M,K] @ (Bh+Bl)[N,K]^T + bias
// tile 128x128, BK=32, 8 warps (32x64 each), 2-stage cp.async.
// ============================================================
#define GBK       32
#define ROWB      80                       // padded row bytes (32 bf16 + 8 pad)
#define TILE_B    (128 * ROWB)             // 10240 B per operand tile
#define AH_OFF    0
#define AL_OFF    (TILE_B)
#define BH_OFF    (2 * TILE_B)
#define BL_OFF    (3 * TILE_B)
#define STAGE_B   (4 * TILE_B)             // 40960
#define GEMM_SMEM (2 * STAGE_B)            // 81920
#define NKCHUNK   (KDIM / GBK)             // 64

__global__ void __launch_bounds__(256)
gemm_hmma_kernel(const __nv_bfloat16* __restrict__ Ah,
                 const __nv_bfloat16* __restrict__ Al,
                 const __nv_bfloat16* __restrict__ Bh,
                 const __nv_bfloat16* __restrict__ Bl,
                 const float* __restrict__ bias,
                 float* __restrict__ C, int N)
{
    extern __shared__ char dsm[];
    const uint32_t sbase = smem_u32(dsm);
    const int tid  = threadIdx.x;
    const int wid  = tid >> 5;
    const int lane = tid & 31;
    const int wm   = wid & 3;        // 4 warps along M
    const int wn   = wid >> 2;       // 2 warps along N
    const int mbase = blockIdx.y * 128;
    const int nbase = blockIdx.x * 128;

    float acc[2][8][4];
    #pragma unroll
    for (int i = 0; i < 2; i++)
        #pragma unroll
        for (int j = 0; j < 8; j++)
            #pragma unroll
            for (int q = 0; q < 4; q++) acc[i][j][q] = 0.0f;

    // ---- stage loader: 4 tiles x 128 rows x 2 chunks(16B)/thread ----
    const __nv_bfloat16* gA[2] = {Ah, Al};
    const __nv_bfloat16* gB[2] = {Bh, Bl};
    auto load_stage = [&](int c, int s) {
        const uint32_t st = sbase + s * STAGE_B;
        const int kb = c * GBK;
        #pragma unroll
        for (int hl = 0; hl < 2; hl++) {
            #pragma unroll
            for (int i = 0; i < 2; i++) {
                int u   = tid + i * 256;        // 0..511
                int row = u >> 2;
                int ch  = u & 3;                // 16B chunk (8 bf16)
                uint32_t so = row * ROWB + ch * 16;
                cp_async16(st + (hl ? AL_OFF : AH_OFF) + so,
                           gA[hl] + (size_t)(mbase + row) * KDIM + kb + ch * 8);
                cp_async16(st + (hl ? BL_OFF : BH_OFF) + so,
                           gB[hl] + (size_t)(nbase + row) * KDIM + kb + ch * 8);
            }
        }
        cp_commit();
    };

    load_stage(0, 0);

    // fragment smem addresses (byte offsets within a tile)
    // A frag (x4): row = mi*16 + ((lane>>3)&1)*8 + (lane&7), byte = (lane>>4)*16 + ks*32
    const int a_r  = ((lane >> 3) & 1) * 8 + (lane & 7);
    const int a_b  = (lane >> 4) * 16;
    // B frag (x4): row = ni*16 + ((lane>>4)&1)*8 + (lane&7), byte = ((lane>>3)&1)*16 + ks*32
    const int b_r  = ((lane >> 4) & 1) * 8 + (lane & 7);
    const int b_b  = ((lane >> 3) & 1) * 16;

    for (int c = 0; c < NKCHUNK; c++) {
        const int s = c & 1;
        if (c + 1 < NKCHUNK) {
            load_stage(c + 1, s ^ 1);
            cp_wait1();
        } else {
            cp_wait0();
        }
        __syncthreads();

        const uint32_t st = sbase + s * STAGE_B;
        #pragma unroll
        for (int ks = 0; ks < 2; ks++) {
            uint32_t afh[2][4], afl[2][4];
            #pragma unroll
            for (int mi = 0; mi < 2; mi++) {
                uint32_t ar = (uint32_t)((wm * 32 + mi * 16 + a_r) * ROWB + a_b + ks * 32);
                ldm_x4(afh[mi], st + AH_OFF + ar);
                ldm_x4(afl[mi], st + AL_OFF + ar);
            }
            #pragma unroll
            for (int ni = 0; ni < 4; ni++) {
                uint32_t br = (uint32_t)((wn * 64 + ni * 16 + b_r) * ROWB + b_b + ks * 32);
                uint32_t bfh[4], bfl[4];
                ldm_x4(bfh, st + BH_OFF + br);
                ldm_x4(bfl, st + BL_OFF + br);
                #pragma unroll
                for (int half = 0; half < 2; half++) {
                    const int nj = ni * 2 + half;
                    #pragma unroll
                    for (int mi = 0; mi < 2; mi++) {
                        mma_bf16(acc[mi][nj], afh[mi], bfh + half * 2);  // hi*hi
                        mma_bf16(acc[mi][nj], afh[mi], bfl + half * 2);  // hi*lo
                        mma_bf16(acc[mi][nj], afl[mi], bfh + half * 2);  // lo*hi
                    }
                }
            }
        }
        __syncthreads();
    }

    // ---- epilogue: bias + store ----
    #pragma unroll
    for (int mi = 0; mi < 2; mi++) {
        #pragma unroll
        for (int nj = 0; nj < 8; nj++) {
            const int col = nbase + wn * 64 + nj * 8 + (lane & 3) * 2;
            const int row = mbase + wm * 32 + mi * 16 + (lane >> 2);
            const float b0 = bias[col], b1 = bias[col + 1];
            float2 v0 = make_float2(acc[mi][nj][0] + b0, acc[mi][nj][1] + b1);
            float2 v1 = make_float2(acc[mi][nj][2] + b0, acc[mi][nj][3] + b1);
            *(float2*)(C + (size_t)row * N + col)       = v0;
            *(float2*)(C + (size_t)(row + 8) * N + col) = v1;
        }
    }
}

// ============================================================
// Flash attention (fp32, non-causal) — unchanged from passing R2 kernel
// ============================================================
#define BQ 64
#define BK 64
#define QPAD 4

struct FlashSmem {
    float Qs[HEAD_DIM][BQ + QPAD];
    float Ks[HEAD_DIM][BK + QPAD];
    float Vs[BK][HEAD_DIM];
    float Ss[BQ][BK + 1];
    float mrow[BQ];
    float lrow[BQ];
    float frow[BQ];
};

__global__ __launch_bounds__(256)
void flash_attn_kernel(const float* __restrict__ Q,
                       const float* __restrict__ K,
                       const float* __restrict__ V,
                       float* __restrict__ O)
{
    extern __shared__ char smem_raw[];
    FlashSmem& sm = *reinterpret_cast<FlashSmem*>(smem_raw);

    const int tid = threadIdx.x;
    const int tx  = tid & 15;
    const int ty  = tid >> 4;
    const int qb  = blockIdx.x;
    const int h   = blockIdx.y;
    const int b   = blockIdx.z;
    const int kvh = h >> 2;

    const size_t q_base = ((size_t)(b * SEQ + qb * BQ)) * HIDDEN + h * HEAD_DIM;
    const size_t k_base = ((size_t)(b * SEQ)) * KVDIM + kvh * HEAD_DIM;

    for (int idx = tid; idx < BQ * HEAD_DIM; idx += 256) {
        int r = idx >> 7;
        int d = idx & 127;
        sm.Qs[d][r] = Q[q_base + (size_t)r * HIDDEN + d] * ATT_SCALE;
    }
    if (tid < BQ) {
        sm.mrow[tid] = -INFINITY;
        sm.lrow[tid] = 0.0f;
    }

    float acc[4][8];
    #pragma unroll
    for (int i = 0; i < 4; i++)
        #pragma unroll
        for (int j = 0; j < 8; j++) acc[i][j] = 0.0f;

    for (int kb = 0; kb < SEQ / BK; kb++) {
        __syncthreads();
        const size_t kv_off = k_base + (size_t)kb * BK * KVDIM;
        for (int idx = tid; idx < BK * HEAD_DIM; idx += 256) {
            int j = idx >> 7;
            int d = idx & 127;
            float kv = K[kv_off + (size_t)j * KVDIM + d];
            float vv = V[kv_off + (size_t)j * KVDIM + d];
            sm.Ks[d][j] = kv;
            sm.Vs[j][d] = vv;
        }
        __syncthreads();

        {
            float s[4][4];
            #pragma unroll
            for (int i = 0; i < 4; i++)
                #pragma unroll
                for (int j = 0; j < 4; j++) s[i][j] = 0.0f;

            #pragma unroll 4
            for (int d = 0; d < HEAD_DIM; d++) {
                float q4[4], k4[4];
                *(float4*)q4 = *(const float4*)&sm.Qs[d][ty * 4];
                *(float4*)k4 = *(const float4*)&sm.Ks[d][tx * 4];
                #pragma unroll
                for (int i = 0; i < 4; i++)
                    #pragma unroll
                    for (int j = 0; j < 4; j++)
                        s[i][j] = fmaf(q4[i], k4[j], s[i][j]);
            }
            #pragma unroll
            for (int i = 0; i < 4; i++)
                #pragma unroll
                for (int j = 0; j < 4; j++)
                    sm.Ss[ty * 4 + i][tx * 4 + j] = s[i][j];
        }
        __syncthreads();

        if (tid < BQ) {
            const int r = tid;
            float rowmax = -INFINITY;
            #pragma unroll 8
            for (int j = 0; j < BK; j++)
                rowmax = fmaxf(rowmax, sm.Ss[r][j]);
            float m_old = sm.mrow[r];
            float m_new = fmaxf(m_old, rowmax);
            float f     = __expf(m_old - m_new);
            float sum   = 0.0f;
            #pragma unroll 8
            for (int j = 0; j < BK; j++) {
                float p = __expf(sm.Ss[r][j] - m_new);
                sm.Ss[r][j] = p;
                sum += p;
            }
            sm.mrow[r] = m_new;
            sm.lrow[r] = sm.lrow[r] * f + sum;
            sm.frow[r] = f;
        }
        __syncthreads();

        float fr[4];
        #pragma unroll
        for (int i = 0; i < 4; i++) fr[i] = sm.frow[ty * 4 + i];
        #pragma unroll
        for (int i = 0; i < 4; i++)
            #pragma unroll
            for (int jj = 0; jj < 8; jj++) acc[i][jj] *= fr[i];

        #pragma unroll 4
        for (int j = 0; j < BK; j++) {
            float p[4];
            #pragma unroll
            for (int i = 0; i < 4; i++) p[i] = sm.Ss[ty * 4 + i][j];
            float v[8];
            *(float4*)(v    ) = *(const float4*)&sm.Vs[j][tx * 8    ];
            *(float4*)(v + 4) = *(const float4*)&sm.Vs[j][tx * 8 + 4];
            #pragma unroll
            for (int i = 0; i < 4; i++)
                #pragma unroll
                for (int jj = 0; jj < 8; jj++)
                    acc[i][jj] = fmaf(p[i], v[jj], acc[i][jj]);
        }
    }

    __syncthreads();
    #pragma unroll
    for (int i = 0; i < 4; i++) {
        const int r = ty * 4 + i;
        const float inv_l = 1.0f / sm.lrow[r];
        float* orow = O + q_base + (size_t)r * HIDDEN + tx * 8;
        #pragma unroll
        for (int jj = 0; jj < 8; jj += 4) {
            float4 v;
            v.x = acc[i][jj + 0] * inv_l;
            v.y = acc[i][jj + 1] * inv_l;
            v.z = acc[i][jj + 2] * inv_l;
            v.w = acc[i][jj + 3] * inv_l;
            *(float4*)(orow + jj) = v;
        }
    }
}

// ============================================================
// launcher
// ============================================================
extern "C" void kernel_launch(void* const* d_in, const int* in_sizes, int n_in,
                              void* d_out, int out_size)
{
    const float* x  = (const float*)d_in[0];
    const float* Wq = (const float*)d_in[1];
    const float* bq = (const float*)d_in[2];
    const float* Wk = (const float*)d_in[3];
    const float* bk = (const float*)d_in[4];
    const float* Wv = (const float*)d_in[5];
    const float* bv = (const float*)d_in[6];
    const float* Wo = (const float*)d_in[7];
    const float* bo = (const float*)d_in[8];
    float* out = (float*)d_out;

    float *dQ, *dK, *dV, *dAO;
    cudaGetSymbolAddress((void**)&dQ,  g_Q);
    cudaGetSymbolAddress((void**)&dK,  g_K);
    cudaGetSymbolAddress((void**)&dV,  g_V);
    cudaGetSymbolAddress((void**)&dAO, g_AO);
    __nv_bfloat16 *xh, *xl, *wqh, *wql, *wkh, *wkl, *wvh, *wvl, *woh, *wol;
    cudaGetSymbolAddress((void**)&xh,  g_xh);
    cudaGetSymbolAddress((void**)&xl,  g_xl);
    cudaGetSymbolAddress((void**)&wqh, g_wqt_h);
    cudaGetSymbolAddress((void**)&wql, g_wqt_l);
    cudaGetSymbolAddress((void**)&wkh, g_wkt_h);
    cudaGetSymbolAddress((void**)&wkl, g_wkt_l);
    cudaGetSymbolAddress((void**)&wvh, g_wvt_h);
    cudaGetSymbolAddress((void**)&wvl, g_wvt_l);
    cudaGetSymbolAddress((void**)&woh, g_wot_h);
    cudaGetSymbolAddress((void**)&wol, g_wot_l);

    cudaFuncSetAttribute(gemm_hmma_kernel,
                         cudaFuncAttributeMaxDynamicSharedMemorySize, GEMM_SMEM);
    cudaFuncSetAttribute(flash_attn_kernel,
                         cudaFuncAttributeMaxDynamicSharedMemorySize,
                         (int)sizeof(FlashSmem));

    // ---- weight transposes + splits ----
    dim3 tt(32, 8);
    transpose_split_kernel<<<dim3(HIDDEN/32, KDIM/32), tt>>>(Wq, wqh, wql, KDIM, HIDDEN);
    transpose_split_kernel<<<dim3(KVDIM /32, KDIM/32), tt>>>(Wk, wkh, wkl, KDIM, KVDIM);
    transpose_split_kernel<<<dim3(KVDIM /32, KDIM/32), tt>>>(Wv, wvh, wvl, KDIM, KVDIM);
    transpose_split_kernel<<<dim3(HIDDEN/32, KDIM/32), tt>>>(Wo, woh, wol, KDIM, HIDDEN);

    // ---- split x ----
    const int n4x = MTOT * HIDDEN / 4;
    split_kernel<<<(n4x + 255) / 256, 256>>>(x, xh, xl, n4x);

    // ---- projections (HMMA bf16x2) ----
    gemm_hmma_kernel<<<dim3(HIDDEN/128, MTOT/128), 256, GEMM_SMEM>>>(xh, xl, wqh, wql, bq, dQ, HIDDEN);
    gemm_hmma_kernel<<<dim3(KVDIM /128, MTOT/128), 256, GEMM_SMEM>>>(xh, xl, wkh, wkl, bk, dK, KVDIM);
    gemm_hmma_kernel<<<dim3(KVDIM /128, MTOT/128), 256, GEMM_SMEM>>>(xh, xl, wvh, wvl, bv, dV, KVDIM);

    // ---- attention ----
    dim3 ga(SEQ / BQ, NUM_HEADS, BATCH);
    flash_attn_kernel<<<ga, 256, sizeof(FlashSmem)>>>(dQ, dK, dV, dAO);

    // ---- split AO (reuse x split buffers) + output projection ----
    split_kernel<<<(n4x + 255) / 256, 256>>>(dAO, xh, xl, n4x);
    gemm_hmma_kernel<<<dim3(HIDDEN/128, MTOT/128), 256, GEMM_SMEM>>>(xh, xl, woh, wol, bo, out, HIDDEN);
}

// round 5
// speedup vs baseline: 3.6613x; 2.5837x over previous
#include <cuda_runtime.h>
#include <cuda_bf16.h>
#include <math.h>
#include <stdint.h>

// ---------------- problem constants ----------------
#define HIDDEN    2048
#define KVDIM     512
#define HEAD_DIM  128
#define NUM_HEADS 16
#define SEQ       2048
#define BATCH     2
#define MTOT      (BATCH * SEQ)          // 4096
#define ATT_SCALE 0.08838834764831845f   // 128^-0.5
#define KDIM      2048

// ---------------- scratch (no allocations allowed) ----------------
__device__ __nv_bfloat16 g_xh [MTOT * HIDDEN];
__device__ __nv_bfloat16 g_xl [MTOT * HIDDEN];
__device__ __nv_bfloat16 g_qh [MTOT * HIDDEN];   // Q (pre-scaled) split
__device__ __nv_bfloat16 g_ql [MTOT * HIDDEN];
__device__ __nv_bfloat16 g_kh [MTOT * KVDIM];
__device__ __nv_bfloat16 g_kl [MTOT * KVDIM];
__device__ __nv_bfloat16 g_vh [MTOT * KVDIM];
__device__ __nv_bfloat16 g_vl [MTOT * KVDIM];
__device__ __nv_bfloat16 g_aoh[MTOT * HIDDEN];   // attention out split
__device__ __nv_bfloat16 g_aol[MTOT * HIDDEN];
__device__ __nv_bfloat16 g_wqt_h[HIDDEN * HIDDEN];
__device__ __nv_bfloat16 g_wqt_l[HIDDEN * HIDDEN];
__device__ __nv_bfloat16 g_wkt_h[KVDIM  * HIDDEN];
__device__ __nv_bfloat16 g_wkt_l[KVDIM  * HIDDEN];
__device__ __nv_bfloat16 g_wvt_h[KVDIM  * HIDDEN];
__device__ __nv_bfloat16 g_wvt_l[KVDIM  * HIDDEN];
__device__ __nv_bfloat16 g_wot_h[HIDDEN * HIDDEN];
__device__ __nv_bfloat16 g_wot_l[HIDDEN * HIDDEN];

// ============================================================
// PTX helpers
// ============================================================
__device__ __forceinline__ uint32_t smem_u32(const void* p) {
    return (uint32_t)__cvta_generic_to_shared(p);
}
__device__ __forceinline__ void cp_async16(uint32_t dst, const void* src) {
    asm volatile("cp.async.cg.shared.global [%0], [%1], 16;"
                 :: "r"(dst), "l"(src) : "memory");
}
__device__ __forceinline__ void cp_commit() {
    asm volatile("cp.async.commit_group;" ::: "memory");
}
__device__ __forceinline__ void cp_wait1() {
    asm volatile("cp.async.wait_group 1;" ::: "memory");
}
__device__ __forceinline__ void cp_wait0() {
    asm volatile("cp.async.wait_group 0;" ::: "memory");
}
__device__ __forceinline__ void ldm_x4(uint32_t* r, uint32_t addr) {
    asm volatile("ldmatrix.sync.aligned.m8n8.x4.shared.b16 {%0,%1,%2,%3}, [%4];"
                 : "=r"(r[0]), "=r"(r[1]), "=r"(r[2]), "=r"(r[3]) : "r"(addr));
}
__device__ __forceinline__ void ldm_x4_t(uint32_t* r, uint32_t addr) {
    asm volatile("ldmatrix.sync.aligned.m8n8.x4.trans.shared.b16 {%0,%1,%2,%3}, [%4];"
                 : "=r"(r[0]), "=r"(r[1]), "=r"(r[2]), "=r"(r[3]) : "r"(addr));
}
__device__ __forceinline__ void mma_bf16(float* c, const uint32_t* a, const uint32_t* b) {
    asm volatile(
        "mma.sync.aligned.m16n8k16.row.col.f32.bf16.bf16.f32 "
        "{%0,%1,%2,%3}, {%4,%5,%6,%7}, {%8,%9}, {%0,%1,%2,%3};"
        : "+f"(c[0]), "+f"(c[1]), "+f"(c[2]), "+f"(c[3])
        : "r"(a[0]), "r"(a[1]), "r"(a[2]), "r"(a[3]), "r"(b[0]), "r"(b[1]));
}
// pack two f32 -> bf16x2 (v0 in low half, v1 in high half)
__device__ __forceinline__ uint32_t cvt_bf16x2(float v1, float v0) {
    uint32_t r;
    asm("cvt.rn.bf16x2.f32 %0, %1, %2;" : "=r"(r) : "f"(v1), "f"(v0));
    return r;
}
// split-write pair (v0,v1) at H[off],L[off] (off must be even)
__device__ __forceinline__ void store_pair(__nv_bfloat16* H, __nv_bfloat16* L,
                                           size_t off, float v0, float v1) {
    uint32_t hh = cvt_bf16x2(v1, v0);
    float h0 = __uint_as_float(hh << 16);
    float h1 = __uint_as_float(hh & 0xffff0000u);
    uint32_t ll = cvt_bf16x2(v1 - h1, v0 - h0);
    *(uint32_t*)(H + off) = hh;
    *(uint32_t*)(L + off) = ll;
}

// ============================================================
// split / transpose kernels
// ============================================================
__global__ void split_kernel(const float* __restrict__ src,
                             __nv_bfloat16* __restrict__ hi,
                             __nv_bfloat16* __restrict__ lo, int n4)
{
    int i = blockIdx.x * 256 + threadIdx.x;
    if (i >= n4) return;
    float4 v = *(const float4*)(src + (size_t)i * 4);
    uint32_t h01 = cvt_bf16x2(v.y, v.x);
    uint32_t h23 = cvt_bf16x2(v.w, v.z);
    float r0 = v.x - __uint_as_float(h01 << 16);
    float r1 = v.y - __uint_as_float(h01 & 0xffff0000u);
    float r2 = v.z - __uint_as_float(h23 << 16);
    float r3 = v.w - __uint_as_float(h23 & 0xffff0000u);
    uint32_t l01 = cvt_bf16x2(r1, r0);
    uint32_t l23 = cvt_bf16x2(r3, r2);
    uint2 hv = make_uint2(h01, h23);
    uint2 lv = make_uint2(l01, l23);
    *(uint2*)(hi + (size_t)i * 4) = hv;
    *(uint2*)(lo + (size_t)i * 4) = lv;
}

__global__ void transpose_split_kernel(const float* __restrict__ W,
                                       __nv_bfloat16* __restrict__ Th,
                                       __nv_bfloat16* __restrict__ Tl,
                                       int Kr, int Nc)
{
    __shared__ float t[32][33];
    const int tx = threadIdx.x;
    const int ty = threadIdx.y;
    const int n0 = blockIdx.x * 32;
    const int k0 = blockIdx.y * 32;

    #pragma unroll
    for (int i = 0; i < 4; i++) {
        int kk = ty + i * 8;
        t[kk][tx] = W[(size_t)(k0 + kk) * Nc + n0 + tx];
    }
    __syncthreads();
    #pragma unroll
    for (int i = 0; i < 4; i++) {
        int rr = ty + i * 8;
        float v = t[tx][rr];
        __nv_bfloat16 h = __float2bfloat16(v);
        __nv_bfloat16 l = __float2bfloat16(v - __bfloat162float(h));
        size_t o = (size_t)(n0 + rr) * Kr + k0 + tx;
        Th[o] = h;
        Tl[o] = l;
    }
}

// ============================================================
// HMMA bf16x2 GEMM, 128x128 tile, BK=32, 8 warps, 2-stage cp.async.
// Epilogue: Cf!=null -> fp32; else bf16 hi/lo split with scale.
// ============================================================
#define GBK       32
#define ROWB      80
#define TILE_B    (128 * ROWB)
#define AH_OFF    0
#define AL_OFF    (TILE_B)
#define BH_OFF    (2 * TILE_B)
#define BL_OFF    (3 * TILE_B)
#define STAGE_B   (4 * TILE_B)
#define GEMM_SMEM (2 * STAGE_B)
#define NKCHUNK   (KDIM / GBK)

__global__ void __launch_bounds__(256)
gemm_hmma_kernel(const __nv_bfloat16* __restrict__ Ah,
                 const __nv_bfloat16* __restrict__ Al,
                 const __nv_bfloat16* __restrict__ Bh,
                 const __nv_bfloat16* __restrict__ Bl,
                 const float* __restrict__ bias,
                 float* __restrict__ Cf,
                 __nv_bfloat16* __restrict__ Ch,
                 __nv_bfloat16* __restrict__ Cl,
                 float scale, int N)
{
    extern __shared__ char dsm[];
    const uint32_t sbase = smem_u32(dsm);
    const int tid  = threadIdx.x;
    const int wid  = tid >> 5;
    const int lane = tid & 31;
    const int wm   = wid & 3;
    const int wn   = wid >> 2;
    const int mbase = blockIdx.y * 128;
    const int nbase = blockIdx.x * 128;

    float acc[2][8][4];
    #pragma unroll
    for (int i = 0; i < 2; i++)
        #pragma unroll
        for (int j = 0; j < 8; j++)
            #pragma unroll
            for (int q = 0; q < 4; q++) acc[i][j][q] = 0.0f;

    const __nv_bfloat16* gA[2] = {Ah, Al};
    const __nv_bfloat16* gB[2] = {Bh, Bl};
    auto load_stage = [&](int c, int s) {
        const uint32_t st = sbase + s * STAGE_B;
        const int kb = c * GBK;
        #pragma unroll
        for (int hl = 0; hl < 2; hl++) {
            #pragma unroll
            for (int i = 0; i < 2; i++) {
                int u   = tid + i * 256;
                int row = u >> 2;
                int ch  = u & 3;
                uint32_t so = row * ROWB + ch * 16;
                cp_async16(st + (hl ? AL_OFF : AH_OFF) + so,
                           gA[hl] + (size_t)(mbase + row) * KDIM + kb + ch * 8);
                cp_async16(st + (hl ? BL_OFF : BH_OFF) + so,
                           gB[hl] + (size_t)(nbase + row) * KDIM + kb + ch * 8);
            }
        }
        cp_commit();
    };

    load_stage(0, 0);

    const int a_r  = ((lane >> 3) & 1) * 8 + (lane & 7);
    const int a_b  = (lane >> 4) * 16;
    const int b_r  = ((lane >> 4) & 1) * 8 + (lane & 7);
    const int b_b  = ((lane >> 3) & 1) * 16;

    for (int c = 0; c < NKCHUNK; c++) {
        const int s = c & 1;
        if (c + 1 < NKCHUNK) {
            load_stage(c + 1, s ^ 1);
            cp_wait1();
        } else {
            cp_wait0();
        }
        __syncthreads();

        const uint32_t st = sbase + s * STAGE_B;
        #pragma unroll
        for (int ks = 0; ks < 2; ks++) {
            uint32_t afh[2][4], afl[2][4];
            #pragma unroll
            for (int mi = 0; mi < 2; mi++) {
                uint32_t ar = (uint32_t)((wm * 32 + mi * 16 + a_r) * ROWB + a_b + ks * 32);
                ldm_x4(afh[mi], st + AH_OFF + ar);
                ldm_x4(afl[mi], st + AL_OFF + ar);
            }
            #pragma unroll
            for (int ni = 0; ni < 4; ni++) {
                uint32_t br = (uint32_t)((wn * 64 + ni * 16 + b_r) * ROWB + b_b + ks * 32);
                uint32_t bfh[4], bfl[4];
                ldm_x4(bfh, st + BH_OFF + br);
                ldm_x4(bfl, st + BL_OFF + br);
                #pragma unroll
                for (int half = 0; half < 2; half++) {
                    const int nj = ni * 2 + half;
                    #pragma unroll
                    for (int mi = 0; mi < 2; mi++) {
                        mma_bf16(acc[mi][nj], afh[mi], bfh + half * 2);
                        mma_bf16(acc[mi][nj], afh[mi], bfl + half * 2);
                        mma_bf16(acc[mi][nj], afl[mi], bfh + half * 2);
                    }
                }
            }
        }
        __syncthreads();
    }

    // ---- epilogue ----
    #pragma unroll
    for (int mi = 0; mi < 2; mi++) {
        #pragma unroll
        for (int nj = 0; nj < 8; nj++) {
            const int col = nbase + wn * 64 + nj * 8 + (lane & 3) * 2;
            const int row = mbase + wm * 32 + mi * 16 + (lane >> 2);
            const float b0 = bias[col], b1 = bias[col + 1];
            float v0 = acc[mi][nj][0] + b0, v1 = acc[mi][nj][1] + b1;
            float v2 = acc[mi][nj][2] + b0, v3 = acc[mi][nj][3] + b1;
            if (Cf) {
                *(float2*)(Cf + (size_t)row * N + col)       = make_float2(v0, v1);
                *(float2*)(Cf + (size_t)(row + 8) * N + col) = make_float2(v2, v3);
            } else {
                store_pair(Ch, Cl, (size_t)row * N + col,       v0 * scale, v1 * scale);
                store_pair(Ch, Cl, (size_t)(row + 8) * N + col, v2 * scale, v3 * scale);
            }
        }
    }
}

// ============================================================
// Flash attention, HMMA bf16x2. BQ=128 (8 warps x 16 rows), BK=64.
// Q persistent in smem; K/V double-buffered cp.async (bf16 hi/lo from global).
// ============================================================
#define FPIT   136                 // bf16 elements per padded row (272 B)
#define FPITB  272
#define QH_OFF 0
#define QTILE  (128 * FPITB)       // 34816
#define KV0_OFF (2 * QTILE)        // 69632
#define KVTILE (64 * FPITB)        // 17408
#define KVSTAGE (4 * KVTILE)       // 69632
#define FLASH_SMEM (KV0_OFF + 2 * KVSTAGE)   // 208896
#define NKB    (SEQ / 64)          // 32

__global__ void __launch_bounds__(256)
flash_hmma_kernel(const __nv_bfloat16* __restrict__ Qh,
                  const __nv_bfloat16* __restrict__ Ql,
                  const __nv_bfloat16* __restrict__ Kh,
                  const __nv_bfloat16* __restrict__ Kl,
                  const __nv_bfloat16* __restrict__ Vh,
                  const __nv_bfloat16* __restrict__ Vl,
                  __nv_bfloat16* __restrict__ AOh,
                  __nv_bfloat16* __restrict__ AOl)
{
    extern __shared__ char dsm[];
    const uint32_t sbase = smem_u32(dsm);
    const int tid  = threadIdx.x;
    const int wid  = tid >> 5;
    const int lane = tid & 31;
    const int qb   = blockIdx.x;        // 0..15
    const int h    = blockIdx.y;        // 0..15
    const int b    = blockIdx.z;        // 0..1
    const int kvh  = h >> 2;

    const size_t qrow0 = (size_t)(b * SEQ + qb * 128);

    // ---- prologue: Q (128 rows x 128 dims, hi+lo) + KV stage 0, one group ----
    {
        const __nv_bfloat16* qops[2] = {Qh, Ql};
        #pragma unroll
        for (int op = 0; op < 2; op++) {
            #pragma unroll
            for (int i = 0; i < 8; i++) {
                int u = tid + i * 256;        // 0..2047
                int row = u >> 4, ch = u & 15;
                cp_async16(sbase + op * QTILE + row * FPITB + ch * 16,
                           qops[op] + (qrow0 + row) * HIDDEN + h * HEAD_DIM + ch * 8);
            }
        }
    }
    const __nv_bfloat16* kvops[4] = {Kh, Kl, Vh, Vl};
    auto load_kv = [&](int c, int s) {
        const uint32_t st = sbase + KV0_OFF + s * KVSTAGE;
        const size_t krow0 = (size_t)(b * SEQ + c * 64);
        #pragma unroll
        for (int op = 0; op < 4; op++) {
            #pragma unroll
            for (int i = 0; i < 4; i++) {
                int u = tid + i * 256;        // 0..1023
                int row = u >> 4, ch = u & 15;
                cp_async16(st + op * KVTILE + row * FPITB + ch * 16,
                           kvops[op] + (krow0 + row) * KVDIM + kvh * HEAD_DIM + ch * 8);
            }
        }
    };
    load_kv(0, 0);
    cp_commit();   // group: Q + KV0

    // fragment lane addressing
    const int a_r = ((lane >> 3) & 1) * 8 + (lane & 7);
    const int a_b = (lane >> 4) * 16;
    const int b_r = ((lane >> 4) & 1) * 8 + (lane & 7);
    const int b_b = ((lane >> 3) & 1) * 16;
    const uint32_t qh_base = sbase + QH_OFF + (wid * 16 + a_r) * FPITB + a_b;

    float o[16][4];
    #pragma unroll
    for (int t = 0; t < 16; t++)
        #pragma unroll
        for (int q = 0; q < 4; q++) o[t][q] = 0.0f;
    float m0 = -INFINITY, m1 = -INFINITY, l0 = 0.0f, l1 = 0.0f;

    for (int c = 0; c < NKB; c++) {
        const int s = c & 1;
        if (c + 1 < NKB) {
            load_kv(c + 1, s ^ 1);
            cp_commit();
            cp_wait1();
        } else {
            cp_wait0();
        }
        __syncthreads();

        const uint32_t st = sbase + KV0_OFF + s * KVSTAGE;

        // ---- S = Q K^T (bf16x2, 3 terms) ----
        float sreg[8][4];
        #pragma unroll
        for (int t = 0; t < 8; t++)
            #pragma unroll
            for (int q = 0; q < 4; q++) sreg[t][q] = 0.0f;

        #pragma unroll
        for (int ks = 0; ks < 8; ks++) {
            uint32_t qfh[4], qfl[4];
            ldm_x4(qfh, qh_base + ks * 32);
            ldm_x4(qfl, qh_base + QTILE + ks * 32);
            #pragma unroll
            for (int ng = 0; ng < 4; ng++) {
                uint32_t ka = st + (ng * 16 + b_r) * FPITB + b_b + ks * 32;
                uint32_t kfh[4], kfl[4];
                ldm_x4(kfh, ka);                 // K hi
                ldm_x4(kfl, ka + KVTILE);        // K lo
                #pragma unroll
                for (int half = 0; half < 2; half++) {
                    const int t = ng * 2 + half;
                    mma_bf16(sreg[t], qfh, kfh + half * 2);
                    mma_bf16(sreg[t], qfh, kfl + half * 2);
                    mma_bf16(sreg[t], qfl, kfh + half * 2);
                }
            }
        }

        // ---- online softmax (rows r=lane>>2 and r+8) ----
        float mx0 = -INFINITY, mx1 = -INFINITY;
        #pragma unroll
        for (int t = 0; t < 8; t++) {
            mx0 = fmaxf(mx0, fmaxf(sreg[t][0], sreg[t][1]));
            mx1 = fmaxf(mx1, fmaxf(sreg[t][2], sreg[t][3]));
        }
        mx0 = fmaxf(mx0, __shfl_xor_sync(0xffffffffu, mx0, 1));
        mx0 = fmaxf(mx0, __shfl_xor_sync(0xffffffffu, mx0, 2));
        mx1 = fmaxf(mx1, __shfl_xor_sync(0xffffffffu, mx1, 1));
        mx1 = fmaxf(mx1, __shfl_xor_sync(0xffffffffu, mx1, 2));
        const float nm0 = fmaxf(m0, mx0), nm1 = fmaxf(m1, mx1);
        const float f0 = __expf(m0 - nm0), f1 = __expf(m1 - nm1);
        m0 = nm0; m1 = nm1;

        float sum0 = 0.0f, sum1 = 0.0f;
        #pragma unroll
        for (int t = 0; t < 8; t++) {
            sreg[t][0] = __expf(sreg[t][0] - nm0);
            sreg[t][1] = __expf(sreg[t][1] - nm0);
            sreg[t][2] = __expf(sreg[t][2] - nm1);
            sreg[t][3] = __expf(sreg[t][3] - nm1);
            sum0 += sreg[t][0] + sreg[t][1];
            sum1 += sreg[t][2] + sreg[t][3];
        }
        sum0 += __shfl_xor_sync(0xffffffffu, sum0, 1);
        sum0 += __shfl_xor_sync(0xffffffffu, sum0, 2);
        sum1 += __shfl_xor_sync(0xffffffffu, sum1, 1);
        sum1 += __shfl_xor_sync(0xffffffffu, sum1, 2);
        l0 = l0 * f0 + sum0;
        l1 = l1 * f1 + sum1;

        #pragma unroll
        for (int t = 0; t < 16; t++) {
            o[t][0] *= f0; o[t][1] *= f0;
            o[t][2] *= f1; o[t][3] *= f1;
        }

        // ---- pack P into bf16 hi/lo A-fragments ----
        uint32_t ph[4][4], pl[4][4];
        #pragma unroll
        for (int pt = 0; pt < 4; pt++) {
            const int t0 = 2 * pt, t1 = 2 * pt + 1;
            const float* s0 = sreg[t0];
            const float* s1 = sreg[t1];
            uint32_t hh;
            hh = cvt_bf16x2(s0[1], s0[0]); ph[pt][0] = hh;
            pl[pt][0] = cvt_bf16x2(s0[1] - __uint_as_float(hh & 0xffff0000u),
                                   s0[0] - __uint_as_float(hh << 16));
            hh = cvt_bf16x2(s0[3], s0[2]); ph[pt][1] = hh;
            pl[pt][1] = cvt_bf16x2(s0[3] - __uint_as_float(hh & 0xffff0000u),
                                   s0[2] - __uint_as_float(hh << 16));
            hh = cvt_bf16x2(s1[1], s1[0]); ph[pt][2] = hh;
            pl[pt][2] = cvt_bf16x2(s1[1] - __uint_as_float(hh & 0xffff0000u),
                                   s1[0] - __uint_as_float(hh << 16));
            hh = cvt_bf16x2(s1[3], s1[2]); ph[pt][3] = hh;
            pl[pt][3] = cvt_bf16x2(s1[3] - __uint_as_float(hh & 0xffff0000u),
                                   s1[2] - __uint_as_float(hh << 16));
        }

        // ---- O += P V (V via ldmatrix.trans; bf16x2, 3 terms) ----
        #pragma unroll
        for (int u = 0; u < 4; u++) {           // key 16-groups
            #pragma unroll
            for (int vg = 0; vg < 8; vg++) {    // dim 16-groups
                uint32_t va = st + 2 * KVTILE + (u * 16 + a_r) * FPITB + a_b + vg * 32;
                uint32_t vfh[4], vfl[4];
                ldm_x4_t(vfh, va);              // V hi
                ldm_x4_t(vfl, va + KVTILE);     // V lo
                #pragma unroll
                for (int half = 0; half < 2; half++) {
                    const int nt = vg * 2 + half;
                    mma_bf16(o[nt], ph[u], vfh + half * 2);
                    mma_bf16(o[nt], ph[u], vfl + half * 2);
                    mma_bf16(o[nt], pl[u], vfh + half * 2);
                }
            }
        }
        __syncthreads();
    }

    // ---- epilogue: normalize, split, store ----
    const float inv0 = 1.0f / l0;
    const float inv1 = 1.0f / l1;
    const size_t row = qrow0 + wid * 16 + (lane >> 2);
    #pragma unroll
    for (int nt = 0; nt < 16; nt++) {
        const int col = h * HEAD_DIM + nt * 8 + (lane & 3) * 2;
        store_pair(AOh, AOl, row * HIDDEN + col,       o[nt][0] * inv0, o[nt][1] * inv0);
        store_pair(AOh, AOl, (row + 8) * HIDDEN + col, o[nt][2] * inv1, o[nt][3] * inv1);
    }
}

// ============================================================
// launcher
// ============================================================
extern "C" void kernel_launch(void* const* d_in, const int* in_sizes, int n_in,
                              void* d_out, int out_size)
{
    const float* x  = (const float*)d_in[0];
    const float* Wq = (const float*)d_in[1];
    const float* bq = (const float*)d_in[2];
    const float* Wk = (const float*)d_in[3];
    const float* bk = (const float*)d_in[4];
    const float* Wv = (const float*)d_in[5];
    const float* bv = (const float*)d_in[6];
    const float* Wo = (const float*)d_in[7];
    const float* bo = (const float*)d_in[8];
    float* out = (float*)d_out;

    __nv_bfloat16 *xh, *xl, *qh, *ql, *kh, *kl, *vh, *vl, *aoh, *aol;
    __nv_bfloat16 *wqh, *wql, *wkh, *wkl, *wvh, *wvl, *woh, *wol;
    cudaGetSymbolAddress((void**)&xh,  g_xh);
    cudaGetSymbolAddress((void**)&xl,  g_xl);
    cudaGetSymbolAddress((void**)&qh,  g_qh);
    cudaGetSymbolAddress((void**)&ql,  g_ql);
    cudaGetSymbolAddress((void**)&kh,  g_kh);
    cudaGetSymbolAddress((void**)&kl,  g_kl);
    cudaGetSymbolAddress((void**)&vh,  g_vh);
    cudaGetSymbolAddress((void**)&vl,  g_vl);
    cudaGetSymbolAddress((void**)&aoh, g_aoh);
    cudaGetSymbolAddress((void**)&aol, g_aol);
    cudaGetSymbolAddress((void**)&wqh, g_wqt_h);
    cudaGetSymbolAddress((void**)&wql, g_wqt_l);
    cudaGetSymbolAddress((void**)&wkh, g_wkt_h);
    cudaGetSymbolAddress((void**)&wkl, g_wkt_l);
    cudaGetSymbolAddress((void**)&wvh, g_wvt_h);
    cudaGetSymbolAddress((void**)&wvl, g_wvt_l);
    cudaGetSymbolAddress((void**)&woh, g_wot_h);
    cudaGetSymbolAddress((void**)&wol, g_wot_l);

    cudaFuncSetAttribute(gemm_hmma_kernel,
                         cudaFuncAttributeMaxDynamicSharedMemorySize, GEMM_SMEM);
    cudaFuncSetAttribute(flash_hmma_kernel,
                         cudaFuncAttributeMaxDynamicSharedMemorySize, FLASH_SMEM);

    // weight transposes + splits
    dim3 tt(32, 8);
    transpose_split_kernel<<<dim3(HIDDEN/32, KDIM/32), tt>>>(Wq, wqh, wql, KDIM, HIDDEN);
    transpose_split_kernel<<<dim3(KVDIM /32, KDIM/32), tt>>>(Wk, wkh, wkl, KDIM, KVDIM);
    transpose_split_kernel<<<dim3(KVDIM /32, KDIM/32), tt>>>(Wv, wvh, wvl, KDIM, KVDIM);
    transpose_split_kernel<<<dim3(HIDDEN/32, KDIM/32), tt>>>(Wo, woh, wol, KDIM, HIDDEN);

    // split x
    const int n4x = MTOT * HIDDEN / 4;
    split_kernel<<<(n4x + 255) / 256, 256>>>(x, xh, xl, n4x);

    // projections -> bf16 hi/lo (Q pre-scaled by ATT_SCALE)
    gemm_hmma_kernel<<<dim3(HIDDEN/128, MTOT/128), 256, GEMM_SMEM>>>(
        xh, xl, wqh, wql, bq, nullptr, qh, ql, ATT_SCALE, HIDDEN);
    gemm_hmma_kernel<<<dim3(KVDIM /128, MTOT/128), 256, GEMM_SMEM>>>(
        xh, xl, wkh, wkl, bk, nullptr, kh, kl, 1.0f, KVDIM);
    gemm_hmma_kernel<<<dim3(KVDIM /128, MTOT/128), 256, GEMM_SMEM>>>(
        xh, xl, wvh, wvl, bv, nullptr, vh, vl, 1.0f, KVDIM);

    // attention (HMMA) -> AO hi/lo
    dim3 ga(SEQ / 128, NUM_HEADS, BATCH);    // 16 x 16 x 2
    flash_hmma_kernel<<<ga, 256, FLASH_SMEM>>>(qh, ql, kh, kl, vh, vl, aoh, aol);

    // output projection -> fp32 out
    gemm_hmma_kernel<<<dim3(HIDDEN/128, MTOT/128), 256, GEMM_SMEM>>>(
        aoh, aol, woh, wol, bo, out, nullptr, nullptr, 1.0f, HIDDEN);
}